// round 1
// baseline (speedup 1.0000x reference)
#include <cuda_runtime.h>
#include <math.h>

#define S_LEN 2048
#define HDIM  2048
#define NB    2
#define NH    16
#define DH    128
#define MROWS (NB * S_LEN)   // 4096

// Scratch buffers (device globals — no allocation in kernel_launch)
__device__ float g_Q[MROWS * HDIM];
__device__ float g_K[MROWS * HDIM];
__device__ float g_V[MROWS * HDIM];
__device__ float g_C[MROWS * HDIM];

// ---------------------------------------------------------------------------
// SGEMM: C[M,N] = A[M,K] @ B[N,K]^T (+ bias), all row-major.
// 128x128 tile, BK=16, 256 threads, 8x8 per thread.
// ---------------------------------------------------------------------------
__device__ __forceinline__ void sgemm_body(const float* __restrict__ A,
                                           const float* __restrict__ B,
                                           const float* __restrict__ bias,
                                           float* __restrict__ C,
                                           int M, int N, int K)
{
    __shared__ float As[16][132];   // pad 132 -> 2-way max conflicts
    __shared__ float Bs[16][132];

    const int tid = threadIdx.x;
    const int tx  = tid & 15;
    const int ty  = tid >> 4;
    const int bm  = blockIdx.y * 128;
    const int bn  = blockIdx.x * 128;

    float acc[8][8];
#pragma unroll
    for (int i = 0; i < 8; i++)
#pragma unroll
        for (int j = 0; j < 8; j++) acc[i][j] = 0.f;

    for (int k0 = 0; k0 < K; k0 += 16) {
#pragma unroll
        for (int it = 0; it < 2; it++) {
            int id = tid + it * 256;      // 0..511 float4 slots (128 rows x 4 f4)
            int r  = id >> 2;
            int c4 = id & 3;
            float4 va = *(const float4*)(A + (size_t)(bm + r) * K + k0 + c4 * 4);
            As[c4 * 4 + 0][r] = va.x;
            As[c4 * 4 + 1][r] = va.y;
            As[c4 * 4 + 2][r] = va.z;
            As[c4 * 4 + 3][r] = va.w;
            float4 vb = *(const float4*)(B + (size_t)(bn + r) * K + k0 + c4 * 4);
            Bs[c4 * 4 + 0][r] = vb.x;
            Bs[c4 * 4 + 1][r] = vb.y;
            Bs[c4 * 4 + 2][r] = vb.z;
            Bs[c4 * 4 + 3][r] = vb.w;
        }
        __syncthreads();

#pragma unroll
        for (int k = 0; k < 16; k++) {
            float ra[8], rb[8];
            *(float4*)&ra[0] = *(const float4*)&As[k][ty * 8];
            *(float4*)&ra[4] = *(const float4*)&As[k][ty * 8 + 4];
            *(float4*)&rb[0] = *(const float4*)&Bs[k][tx * 8];
            *(float4*)&rb[4] = *(const float4*)&Bs[k][tx * 8 + 4];
#pragma unroll
            for (int i = 0; i < 8; i++)
#pragma unroll
                for (int j = 0; j < 8; j++)
                    acc[i][j] += ra[i] * rb[j];
        }
        __syncthreads();
    }

#pragma unroll
    for (int i = 0; i < 8; i++) {
        int row = bm + ty * 8 + i;
#pragma unroll
        for (int j = 0; j < 8; j += 4) {
            int col = bn + tx * 8 + j;
            float4 v;
            v.x = acc[i][j];
            v.y = acc[i][j + 1];
            v.z = acc[i][j + 2];
            v.w = acc[i][j + 3];
            if (bias) {
                v.x += bias[col];
                v.y += bias[col + 1];
                v.z += bias[col + 2];
                v.w += bias[col + 3];
            }
            *(float4*)(C + (size_t)row * N + col) = v;
        }
    }
}

__global__ void __launch_bounds__(256) qkv_gemm_kernel(
    const float* __restrict__ X,
    const float* __restrict__ Wq,
    const float* __restrict__ Wk,
    const float* __restrict__ Wv)
{
    const float* B = (blockIdx.z == 0) ? Wq : (blockIdx.z == 1) ? Wk : Wv;
    float* C       = (blockIdx.z == 0) ? g_Q : (blockIdx.z == 1) ? g_K : g_V;
    sgemm_body(X, B, nullptr, C, MROWS, HDIM, HDIM);
}

__global__ void __launch_bounds__(256) out_gemm_kernel(
    const float* __restrict__ Wo,
    const float* __restrict__ bo,
    float* __restrict__ out)
{
    sgemm_body(g_C, Wo, bo, out, MROWS, HDIM, HDIM);
}

// ---------------------------------------------------------------------------
// RoPE applied in-place to g_Q and g_K.
// One thread per (row m, head h, dim d<64).
// ---------------------------------------------------------------------------
__global__ void rope_kernel(const int* __restrict__ pos_ids)
{
    int idx = blockIdx.x * 256 + threadIdx.x;
    if (idx >= MROWS * NH * 64) return;
    int d = idx & 63;
    int h = (idx >> 6) & 15;
    int m = idx >> 10;
    int s = m & (S_LEN - 1);

    float p = (float)pos_ids[s];
    // theta = 10000^(-d/64) = exp(-ln(1e4)/64 * d)
    float theta = expf(-0.14391156531392624f * (float)d);
    float ang = p * theta;
    float sn, cs;
    sincosf(ang, &sn, &cs);

    size_t base = (size_t)m * HDIM + h * DH + d;
    float q1 = g_Q[base], q2 = g_Q[base + 64];
    g_Q[base]      = q1 * cs - q2 * sn;
    g_Q[base + 64] = q1 * sn + q2 * cs;
    float k1 = g_K[base], k2 = g_K[base + 64];
    g_K[base]      = k1 * cs - k2 * sn;
    g_K[base + 64] = k1 * sn + k2 * cs;
}

// ---------------------------------------------------------------------------
// Flash attention, fp32, causal. 64 q-rows x 64 k-cols tiles, dh=128.
// Block 256 threads: scores thread = (q: ty*4+i, k: tx*4+j);
// output thread = (q: ty*4+i, d: j*16+tx). Same q rows -> m/l live in regs.
// K stored d-major with pad 65 for conflict-light reads.
// ---------------------------------------------------------------------------
#define ATT_SMEM_FLOATS (64 * 128 + 128 * 65 + 64 * 128 + 64 * 64)
#define ATT_SMEM_BYTES  (ATT_SMEM_FLOATS * 4)

__global__ void __launch_bounds__(256) attn_kernel()
{
    extern __shared__ float sm[];
    float* Qs = sm;                 // [64][128]
    float* Kt = Qs + 64 * 128;      // [128][65]  (d-major, padded)
    float* Vs = Kt + 128 * 65;      // [64][128]
    float* Ps = Vs + 64 * 128;      // [64][64]

    const int tid = threadIdx.x;
    const int tx  = tid & 15;
    const int ty  = tid >> 4;
    const int qt  = blockIdx.x;
    const int h   = blockIdx.y;
    const int n   = blockIdx.z;
    const int q0  = qt * 64;
    const float rs = 0.08838834764831845f;   // 1/sqrt(128)

    const size_t rowbase = (size_t)n * S_LEN;
    const size_t hoff    = (size_t)h * DH;

    // Load Q tile (pre-scaled)
#pragma unroll
    for (int it = 0; it < 8; it++) {
        int id = tid + it * 256;        // 2048 float4 slots = 64 rows x 32 f4
        int q  = id >> 5;
        int d0 = (id & 31) << 2;
        float4 v = *(const float4*)(g_Q + (rowbase + q0 + q) * HDIM + hoff + d0);
        v.x *= rs; v.y *= rs; v.z *= rs; v.w *= rs;
        *(float4*)&Qs[q * 128 + d0] = v;
    }

    float m_i[4], l_i[4], acco[4][8];
#pragma unroll
    for (int i = 0; i < 4; i++) {
        m_i[i] = -1e30f;
        l_i[i] = 0.f;
#pragma unroll
        for (int j = 0; j < 8; j++) acco[i][j] = 0.f;
    }

    for (int kt = 0; kt <= qt; kt++) {
        __syncthreads();   // protect Vs/Ps from previous iteration
        int k0 = kt * 64;
#pragma unroll
        for (int it = 0; it < 8; it++) {
            int id = tid + it * 256;
            int k  = id >> 5;
            int d0 = (id & 31) << 2;
            size_t g = (rowbase + k0 + k) * HDIM + hoff + d0;
            float4 vk = *(const float4*)(g_K + g);
            Kt[(d0 + 0) * 65 + k] = vk.x;
            Kt[(d0 + 1) * 65 + k] = vk.y;
            Kt[(d0 + 2) * 65 + k] = vk.z;
            Kt[(d0 + 3) * 65 + k] = vk.w;
            float4 vv = *(const float4*)(g_V + g);
            *(float4*)&Vs[k * 128 + d0] = vv;
        }
        __syncthreads();

        // S = Q K^T  (4x4 per thread)
        float accs[4][4];
#pragma unroll
        for (int i = 0; i < 4; i++)
#pragma unroll
            for (int j = 0; j < 4; j++) accs[i][j] = 0.f;

#pragma unroll 4
        for (int d = 0; d < 128; d++) {
            float rq[4], rk[4];
#pragma unroll
            for (int i = 0; i < 4; i++) rq[i] = Qs[(ty * 4 + i) * 128 + d];
#pragma unroll
            for (int j = 0; j < 4; j++) rk[j] = Kt[d * 65 + tx * 4 + j];
#pragma unroll
            for (int i = 0; i < 4; i++)
#pragma unroll
                for (int j = 0; j < 4; j++)
                    accs[i][j] += rq[i] * rk[j];
        }

        // Causal mask (diagonal tile only)
        if (kt == qt) {
#pragma unroll
            for (int i = 0; i < 4; i++)
#pragma unroll
                for (int j = 0; j < 4; j++)
                    if (ty * 4 + i < tx * 4 + j) accs[i][j] = -1e30f;
        }

        // Online softmax per row (rows = ty*4+i; reduce over 16 tx lanes)
#pragma unroll
        for (int i = 0; i < 4; i++) {
            float mx = fmaxf(fmaxf(accs[i][0], accs[i][1]),
                             fmaxf(accs[i][2], accs[i][3]));
#pragma unroll
            for (int o = 8; o; o >>= 1)
                mx = fmaxf(mx, __shfl_xor_sync(0xffffffffu, mx, o));
            float newm  = fmaxf(m_i[i], mx);
            float alpha = __expf(m_i[i] - newm);
            float rsum  = 0.f;
#pragma unroll
            for (int j = 0; j < 4; j++) {
                float p = __expf(accs[i][j] - newm);
                Ps[(ty * 4 + i) * 64 + tx * 4 + j] = p;
                rsum += p;
            }
#pragma unroll
            for (int o = 8; o; o >>= 1)
                rsum += __shfl_xor_sync(0xffffffffu, rsum, o);
            l_i[i] = l_i[i] * alpha + rsum;
            m_i[i] = newm;
#pragma unroll
            for (int j = 0; j < 8; j++) acco[i][j] *= alpha;
        }
        __syncthreads();   // Ps visible

        // O += P V  (4 q-rows x 8 d-cols per thread; d = j*16+tx -> conflict-free)
#pragma unroll 2
        for (int k = 0; k < 64; k++) {
            float rv[8];
#pragma unroll
            for (int j = 0; j < 8; j++) rv[j] = Vs[k * 128 + j * 16 + tx];
#pragma unroll
            for (int i = 0; i < 4; i++) {
                float p = Ps[(ty * 4 + i) * 64 + k];
#pragma unroll
                for (int j = 0; j < 8; j++) acco[i][j] += p * rv[j];
            }
        }
    }

    // Normalize and write context
#pragma unroll
    for (int i = 0; i < 4; i++) {
        float inv = 1.f / l_i[i];
        size_t row = (rowbase + q0 + ty * 4 + i) * HDIM + hoff;
#pragma unroll
        for (int j = 0; j < 8; j++)
            g_C[row + j * 16 + tx] = acco[i][j] * inv;
    }
}

// ---------------------------------------------------------------------------
// kernel_launch: QKV gemm -> RoPE -> flash attention -> output gemm
// Inputs: 0=X 1=position_ids 2=mask(unused,causal) 3=Wq 4=Wk 5=Wv 6=Wo 7=bo
// ---------------------------------------------------------------------------
extern "C" void kernel_launch(void* const* d_in, const int* in_sizes, int n_in,
                              void* d_out, int out_size)
{
    const float* X   = (const float*)d_in[0];
    const int*   pos = (const int*)d_in[1];
    const float* Wq  = (const float*)d_in[3];
    const float* Wk  = (const float*)d_in[4];
    const float* Wv  = (const float*)d_in[5];
    const float* Wo  = (const float*)d_in[6];
    const float* bo  = (const float*)d_in[7];
    float* out = (float*)d_out;

    cudaFuncSetAttribute(attn_kernel,
                         cudaFuncAttributeMaxDynamicSharedMemorySize,
                         ATT_SMEM_BYTES);

    dim3 g_qkv(HDIM / 128, MROWS / 128, 3);
    qkv_gemm_kernel<<<g_qkv, 256>>>(X, Wq, Wk, Wv);

    int rope_threads = MROWS * NH * 64;
    rope_kernel<<<(rope_threads + 255) / 256, 256>>>(pos);

    dim3 g_att(S_LEN / 64, NH, NB);
    attn_kernel<<<g_att, 256, ATT_SMEM_BYTES>>>();

    dim3 g_out(HDIM / 128, MROWS / 128);
    out_gemm_kernel<<<g_out, 256>>>(Wo, bo, out);
}

// round 2
// speedup vs baseline: 1.9094x; 1.9094x over previous
#include <cuda_runtime.h>
#include <math.h>
#include <stdint.h>

#define S_LEN 2048
#define HDIM  2048
#define NB    2
#define NH    16
#define DH    128
#define MROWS (NB * S_LEN)   // 4096

// Scratch buffers (device globals — no allocation in kernel_launch)
__device__ float g_Q[MROWS * HDIM];
__device__ float g_K[MROWS * HDIM];
__device__ float g_V[MROWS * HDIM];
__device__ float g_C[MROWS * HDIM];

// ---------------------------------------------------------------------------
// TF32 helpers
// ---------------------------------------------------------------------------
__device__ __forceinline__ float f2tf32(float x)
{
    unsigned u;
    asm("cvt.rna.tf32.f32 %0, %1;" : "=r"(u) : "f"(x));
    return __uint_as_float(u);
}

// D += A(m16k8,row) * B(k8n8,col)  in tf32, fp32 accumulate.
// a0=(g,t) a1=(g+8,t) a2=(g,t+4) a3=(g+8,t+4); b0=(t,g) b1=(t+4,g)
__device__ __forceinline__ void mma_tf32(float* c, uint2 alo, uint2 ahi, uint2 b)
{
    asm("mma.sync.aligned.m16n8k8.row.col.f32.tf32.tf32.f32 "
        "{%0,%1,%2,%3}, {%4,%5,%6,%7}, {%8,%9}, {%0,%1,%2,%3};"
        : "+f"(c[0]), "+f"(c[1]), "+f"(c[2]), "+f"(c[3])
        : "r"(alo.x), "r"(ahi.x), "r"(alo.y), "r"(ahi.y),
          "r"(b.x),  "r"(b.y));
}

// ---------------------------------------------------------------------------
// TF32 GEMM: C[M,N] = A[M,K] @ B[N,K]^T (+ bias). 128x128 tile, BK=32,
// 256 threads = 8 warps (2m x 4n), warp tile 64x32, m16n8k8 fragments.
// Smem layout: 4 chunks of k8, each [128 rows][8 k-permuted], chunk stride
// 1034 floats (pad) -> STS and LDS both bank-conflict-free.
// k-permutation within a chunk: k = c (0..7) stored at p = 2*(c&3) + (c>>2),
// so the fragment pair {t, t+4} is one float2 at [row][2t].
// ---------------------------------------------------------------------------
#define CHUNK 1034

__device__ __forceinline__ void mma_gemm_body(const float* __restrict__ A,
                                              const float* __restrict__ B,
                                              const float* __restrict__ bias,
                                              float* __restrict__ C,
                                              int K, int N)
{
    __shared__ float As[4 * CHUNK];
    __shared__ float Bs[4 * CHUNK];

    const int tid    = threadIdx.x;
    const int lane   = tid & 31;
    const int wid    = tid >> 5;
    const int warp_m = wid >> 2;    // 0..1
    const int warp_n = wid & 3;     // 0..3
    const int g      = lane >> 2;   // 0..7
    const int t      = lane & 3;    // 0..3
    const int bm     = blockIdx.y * 128;
    const int bn     = blockIdx.x * 128;

    float acc[4][4][4];
#pragma unroll
    for (int mt = 0; mt < 4; mt++)
#pragma unroll
        for (int nt = 0; nt < 4; nt++)
#pragma unroll
            for (int i = 0; i < 4; i++) acc[mt][nt][i] = 0.f;

    const float* Ab = A + (size_t)bm * K;
    const float* Bb = B + (size_t)bn * K;

    int rr[4], so[4], ko4[4];
#pragma unroll
    for (int it = 0; it < 4; it++) {
        int id  = tid + it * 256;       // 0..1023 float4 slots
        int r   = id >> 3;              // row 0..127
        int f4  = id & 7;               // which float4 in the 32-k row
        rr[it]  = r;
        ko4[it] = f4 * 4;
        so[it]  = (f4 >> 1) * CHUNK + r * 8 + (f4 & 1);
    }

    float4 a4[4], b4[4];
#pragma unroll
    for (int it = 0; it < 4; it++) {
        a4[it] = *(const float4*)(Ab + (size_t)rr[it] * K + ko4[it]);
        b4[it] = *(const float4*)(Bb + (size_t)rr[it] * K + ko4[it]);
    }

    const int nk = K / 32;
    for (int kt = 0; kt < nk; kt++) {
        __syncthreads();   // previous compute done, smem reusable
#pragma unroll
        for (int it = 0; it < 4; it++) {
            As[so[it] + 0] = f2tf32(a4[it].x);
            As[so[it] + 2] = f2tf32(a4[it].y);
            As[so[it] + 4] = f2tf32(a4[it].z);
            As[so[it] + 6] = f2tf32(a4[it].w);
            Bs[so[it] + 0] = f2tf32(b4[it].x);
            Bs[so[it] + 2] = f2tf32(b4[it].y);
            Bs[so[it] + 4] = f2tf32(b4[it].z);
            Bs[so[it] + 6] = f2tf32(b4[it].w);
        }
        __syncthreads();

        if (kt + 1 < nk) {
            int kg = (kt + 1) * 32;
#pragma unroll
            for (int it = 0; it < 4; it++) {
                a4[it] = *(const float4*)(Ab + (size_t)rr[it] * K + kg + ko4[it]);
                b4[it] = *(const float4*)(Bb + (size_t)rr[it] * K + kg + ko4[it]);
            }
        }

#pragma unroll
        for (int k8 = 0; k8 < 4; k8++) {
            const int co = k8 * CHUNK;
            uint2 af[4][2], bf[4];
#pragma unroll
            for (int mt = 0; mt < 4; mt++) {
                const float* p = &As[co + (warp_m * 64 + mt * 16 + g) * 8 + 2 * t];
                af[mt][0] = *(const uint2*)p;
                af[mt][1] = *(const uint2*)(p + 64);   // rows +8
            }
#pragma unroll
            for (int nt = 0; nt < 4; nt++)
                bf[nt] = *(const uint2*)&Bs[co + (warp_n * 32 + nt * 8 + g) * 8 + 2 * t];
#pragma unroll
            for (int mt = 0; mt < 4; mt++)
#pragma unroll
                for (int nt = 0; nt < 4; nt++)
                    mma_tf32(acc[mt][nt], af[mt][0], af[mt][1], bf[nt]);
        }
    }

    // Epilogue: c0,c1 at (g, 2t..2t+1); c2,c3 at (g+8, ...)
#pragma unroll
    for (int mt = 0; mt < 4; mt++) {
        int row = bm + warp_m * 64 + mt * 16 + g;
#pragma unroll
        for (int nt = 0; nt < 4; nt++) {
            int col = bn + warp_n * 32 + nt * 8 + 2 * t;
            float b0 = 0.f, b1 = 0.f;
            if (bias) { b0 = bias[col]; b1 = bias[col + 1]; }
            float2 v0 = make_float2(acc[mt][nt][0] + b0, acc[mt][nt][1] + b1);
            float2 v1 = make_float2(acc[mt][nt][2] + b0, acc[mt][nt][3] + b1);
            *(float2*)(C + (size_t)row * N + col)       = v0;
            *(float2*)(C + (size_t)(row + 8) * N + col) = v1;
        }
    }
}

__global__ void __launch_bounds__(256) qkv_gemm_kernel(
    const float* __restrict__ X,
    const float* __restrict__ Wq,
    const float* __restrict__ Wk,
    const float* __restrict__ Wv)
{
    const float* B = (blockIdx.z == 0) ? Wq : (blockIdx.z == 1) ? Wk : Wv;
    float* C       = (blockIdx.z == 0) ? g_Q : (blockIdx.z == 1) ? g_K : g_V;
    mma_gemm_body(X, B, nullptr, C, HDIM, HDIM);
}

__global__ void __launch_bounds__(256) out_gemm_kernel(
    const float* __restrict__ Wo,
    const float* __restrict__ bo,
    float* __restrict__ out)
{
    mma_gemm_body(g_C, Wo, bo, out, HDIM, HDIM);
}

// ---------------------------------------------------------------------------
// RoPE applied in-place to g_Q and g_K.
// ---------------------------------------------------------------------------
__global__ void rope_kernel(const int* __restrict__ pos_ids)
{
    int idx = blockIdx.x * 256 + threadIdx.x;
    if (idx >= MROWS * NH * 64) return;
    int d = idx & 63;
    int h = (idx >> 6) & 15;
    int m = idx >> 10;
    int s = m & (S_LEN - 1);

    float p = (float)pos_ids[s];
    float theta = expf(-0.14391156531392624f * (float)d);
    float ang = p * theta;
    float sn, cs;
    sincosf(ang, &sn, &cs);

    size_t base = (size_t)m * HDIM + h * DH + d;
    float q1 = g_Q[base], q2 = g_Q[base + 64];
    g_Q[base]      = q1 * cs - q2 * sn;
    g_Q[base + 64] = q1 * sn + q2 * cs;
    float k1 = g_K[base], k2 = g_K[base + 64];
    g_K[base]      = k1 * cs - k2 * sn;
    g_K[base + 64] = k1 * sn + k2 * cs;
}

// ---------------------------------------------------------------------------
// Flash attention, fp32, causal. (unchanged from R1)
// ---------------------------------------------------------------------------
#define ATT_SMEM_FLOATS (64 * 128 + 128 * 65 + 64 * 128 + 64 * 64)
#define ATT_SMEM_BYTES  (ATT_SMEM_FLOATS * 4)

__global__ void __launch_bounds__(256) attn_kernel()
{
    extern __shared__ float sm[];
    float* Qs = sm;                 // [64][128]
    float* Kt = Qs + 64 * 128;      // [128][65]  (d-major, padded)
    float* Vs = Kt + 128 * 65;      // [64][128]
    float* Ps = Vs + 64 * 128;      // [64][64]

    const int tid = threadIdx.x;
    const int tx  = tid & 15;
    const int ty  = tid >> 4;
    const int qt  = blockIdx.x;
    const int h   = blockIdx.y;
    const int n   = blockIdx.z;
    const int q0  = qt * 64;
    const float rs = 0.08838834764831845f;   // 1/sqrt(128)

    const size_t rowbase = (size_t)n * S_LEN;
    const size_t hoff    = (size_t)h * DH;

#pragma unroll
    for (int it = 0; it < 8; it++) {
        int id = tid + it * 256;
        int q  = id >> 5;
        int d0 = (id & 31) << 2;
        float4 v = *(const float4*)(g_Q + (rowbase + q0 + q) * HDIM + hoff + d0);
        v.x *= rs; v.y *= rs; v.z *= rs; v.w *= rs;
        *(float4*)&Qs[q * 128 + d0] = v;
    }

    float m_i[4], l_i[4], acco[4][8];
#pragma unroll
    for (int i = 0; i < 4; i++) {
        m_i[i] = -1e30f;
        l_i[i] = 0.f;
#pragma unroll
        for (int j = 0; j < 8; j++) acco[i][j] = 0.f;
    }

    for (int kt = 0; kt <= qt; kt++) {
        __syncthreads();
        int k0 = kt * 64;
#pragma unroll
        for (int it = 0; it < 8; it++) {
            int id = tid + it * 256;
            int k  = id >> 5;
            int d0 = (id & 31) << 2;
            size_t gg = (rowbase + k0 + k) * HDIM + hoff + d0;
            float4 vk = *(const float4*)(g_K + gg);
            Kt[(d0 + 0) * 65 + k] = vk.x;
            Kt[(d0 + 1) * 65 + k] = vk.y;
            Kt[(d0 + 2) * 65 + k] = vk.z;
            Kt[(d0 + 3) * 65 + k] = vk.w;
            float4 vv = *(const float4*)(g_V + gg);
            *(float4*)&Vs[k * 128 + d0] = vv;
        }
        __syncthreads();

        float accs[4][4];
#pragma unroll
        for (int i = 0; i < 4; i++)
#pragma unroll
            for (int j = 0; j < 4; j++) accs[i][j] = 0.f;

#pragma unroll 4
        for (int d = 0; d < 128; d++) {
            float rq[4], rk[4];
#pragma unroll
            for (int i = 0; i < 4; i++) rq[i] = Qs[(ty * 4 + i) * 128 + d];
#pragma unroll
            for (int j = 0; j < 4; j++) rk[j] = Kt[d * 65 + tx * 4 + j];
#pragma unroll
            for (int i = 0; i < 4; i++)
#pragma unroll
                for (int j = 0; j < 4; j++)
                    accs[i][j] += rq[i] * rk[j];
        }

        if (kt == qt) {
#pragma unroll
            for (int i = 0; i < 4; i++)
#pragma unroll
                for (int j = 0; j < 4; j++)
                    if (ty * 4 + i < tx * 4 + j) accs[i][j] = -1e30f;
        }

#pragma unroll
        for (int i = 0; i < 4; i++) {
            float mx = fmaxf(fmaxf(accs[i][0], accs[i][1]),
                             fmaxf(accs[i][2], accs[i][3]));
#pragma unroll
            for (int o = 8; o; o >>= 1)
                mx = fmaxf(mx, __shfl_xor_sync(0xffffffffu, mx, o));
            float newm  = fmaxf(m_i[i], mx);
            float alpha = __expf(m_i[i] - newm);
            float rsum  = 0.f;
#pragma unroll
            for (int j = 0; j < 4; j++) {
                float p = __expf(accs[i][j] - newm);
                Ps[(ty * 4 + i) * 64 + tx * 4 + j] = p;
                rsum += p;
            }
#pragma unroll
            for (int o = 8; o; o >>= 1)
                rsum += __shfl_xor_sync(0xffffffffu, rsum, o);
            l_i[i] = l_i[i] * alpha + rsum;
            m_i[i] = newm;
#pragma unroll
            for (int j = 0; j < 8; j++) acco[i][j] *= alpha;
        }
        __syncthreads();

#pragma unroll 2
        for (int k = 0; k < 64; k++) {
            float rv[8];
#pragma unroll
            for (int j = 0; j < 8; j++) rv[j] = Vs[k * 128 + j * 16 + tx];
#pragma unroll
            for (int i = 0; i < 4; i++) {
                float p = Ps[(ty * 4 + i) * 64 + k];
#pragma unroll
                for (int j = 0; j < 8; j++) acco[i][j] += p * rv[j];
            }
        }
    }

#pragma unroll
    for (int i = 0; i < 4; i++) {
        float inv = 1.f / l_i[i];
        size_t row = (rowbase + q0 + ty * 4 + i) * HDIM + hoff;
#pragma unroll
        for (int j = 0; j < 8; j++)
            g_C[row + j * 16 + tx] = acco[i][j] * inv;
    }
}

// ---------------------------------------------------------------------------
// kernel_launch: QKV gemm -> RoPE -> flash attention -> output gemm
// Inputs: 0=X 1=position_ids 2=mask(unused,causal) 3=Wq 4=Wk 5=Wv 6=Wo 7=bo
// ---------------------------------------------------------------------------
extern "C" void kernel_launch(void* const* d_in, const int* in_sizes, int n_in,
                              void* d_out, int out_size)
{
    const float* X   = (const float*)d_in[0];
    const int*   pos = (const int*)d_in[1];
    const float* Wq  = (const float*)d_in[3];
    const float* Wk  = (const float*)d_in[4];
    const float* Wv  = (const float*)d_in[5];
    const float* Wo  = (const float*)d_in[6];
    const float* bo  = (const float*)d_in[7];
    float* out = (float*)d_out;

    cudaFuncSetAttribute(attn_kernel,
                         cudaFuncAttributeMaxDynamicSharedMemorySize,
                         ATT_SMEM_BYTES);

    dim3 g_qkv(HDIM / 128, MROWS / 128, 3);
    qkv_gemm_kernel<<<g_qkv, 256>>>(X, Wq, Wk, Wv);

    int rope_threads = MROWS * NH * 64;
    rope_kernel<<<(rope_threads + 255) / 256, 256>>>(pos);

    dim3 g_att(S_LEN / 64, NH, NB);
    attn_kernel<<<g_att, 256, ATT_SMEM_BYTES>>>();

    dim3 g_out(HDIM / 128, MROWS / 128);
    out_gemm_kernel<<<g_out, 256>>>(Wo, bo, out);
}

// round 3
// speedup vs baseline: 3.2132x; 1.6829x over previous
#include <cuda_runtime.h>
#include <math.h>
#include <stdint.h>

#define S_LEN 2048
#define HDIM  2048
#define NB    2
#define NH    16
#define DH    128
#define MROWS (NB * S_LEN)   // 4096

__device__ float g_Q[MROWS * HDIM];
__device__ float g_K[MROWS * HDIM];
__device__ float g_V[MROWS * HDIM];
__device__ float g_C[MROWS * HDIM];

// ---------------------------------------------------------------------------
// TF32 helpers
// ---------------------------------------------------------------------------
__device__ __forceinline__ float f2tf32(float x)
{
    unsigned u;
    asm("cvt.rna.tf32.f32 %0, %1;" : "=r"(u) : "f"(x));
    return __uint_as_float(u);
}

// D += A(m16k8,row) * B(k8n8,col) tf32, fp32 accum.
// a0=(g,t) a1=(g+8,t) a2=(g,t+4) a3=(g+8,t+4); b0=(t,g) b1=(t+4,g)
__device__ __forceinline__ void mma_tf32(float* c, uint2 alo, uint2 ahi, uint2 b)
{
    asm("mma.sync.aligned.m16n8k8.row.col.f32.tf32.tf32.f32 "
        "{%0,%1,%2,%3}, {%4,%5,%6,%7}, {%8,%9}, {%0,%1,%2,%3};"
        : "+f"(c[0]), "+f"(c[1]), "+f"(c[2]), "+f"(c[3])
        : "r"(alo.x), "r"(ahi.x), "r"(alo.y), "r"(ahi.y),
          "r"(b.x),  "r"(b.y));
}

__device__ __forceinline__ void mma_tf32_r(float* c, float a0, float a1,
                                           float a2, float a3,
                                           float b0, float b1)
{
    asm("mma.sync.aligned.m16n8k8.row.col.f32.tf32.tf32.f32 "
        "{%0,%1,%2,%3}, {%4,%5,%6,%7}, {%8,%9}, {%0,%1,%2,%3};"
        : "+f"(c[0]), "+f"(c[1]), "+f"(c[2]), "+f"(c[3])
        : "r"(__float_as_uint(a0)), "r"(__float_as_uint(a1)),
          "r"(__float_as_uint(a2)), "r"(__float_as_uint(a3)),
          "r"(__float_as_uint(b0)), "r"(__float_as_uint(b1)));
}

// ---------------------------------------------------------------------------
// TF32 GEMM (unchanged from R2): C[M,N] = A[M,K] @ B[N,K]^T (+ bias)
// ---------------------------------------------------------------------------
#define CHUNK 1034

__device__ __forceinline__ void mma_gemm_body(const float* __restrict__ A,
                                              const float* __restrict__ B,
                                              const float* __restrict__ bias,
                                              float* __restrict__ C,
                                              int K, int N)
{
    __shared__ float As[4 * CHUNK];
    __shared__ float Bs[4 * CHUNK];

    const int tid    = threadIdx.x;
    const int lane   = tid & 31;
    const int wid    = tid >> 5;
    const int warp_m = wid >> 2;
    const int warp_n = wid & 3;
    const int g      = lane >> 2;
    const int t      = lane & 3;
    const int bm     = blockIdx.y * 128;
    const int bn     = blockIdx.x * 128;

    float acc[4][4][4];
#pragma unroll
    for (int mt = 0; mt < 4; mt++)
#pragma unroll
        for (int nt = 0; nt < 4; nt++)
#pragma unroll
            for (int i = 0; i < 4; i++) acc[mt][nt][i] = 0.f;

    const float* Ab = A + (size_t)bm * K;
    const float* Bb = B + (size_t)bn * K;

    int rr[4], so[4], ko4[4];
#pragma unroll
    for (int it = 0; it < 4; it++) {
        int id  = tid + it * 256;
        int r   = id >> 3;
        int f4  = id & 7;
        rr[it]  = r;
        ko4[it] = f4 * 4;
        so[it]  = (f4 >> 1) * CHUNK + r * 8 + (f4 & 1);
    }

    float4 a4[4], b4[4];
#pragma unroll
    for (int it = 0; it < 4; it++) {
        a4[it] = *(const float4*)(Ab + (size_t)rr[it] * K + ko4[it]);
        b4[it] = *(const float4*)(Bb + (size_t)rr[it] * K + ko4[it]);
    }

    const int nk = K / 32;
    for (int kt = 0; kt < nk; kt++) {
        __syncthreads();
#pragma unroll
        for (int it = 0; it < 4; it++) {
            As[so[it] + 0] = f2tf32(a4[it].x);
            As[so[it] + 2] = f2tf32(a4[it].y);
            As[so[it] + 4] = f2tf32(a4[it].z);
            As[so[it] + 6] = f2tf32(a4[it].w);
            Bs[so[it] + 0] = f2tf32(b4[it].x);
            Bs[so[it] + 2] = f2tf32(b4[it].y);
            Bs[so[it] + 4] = f2tf32(b4[it].z);
            Bs[so[it] + 6] = f2tf32(b4[it].w);
        }
        __syncthreads();

        if (kt + 1 < nk) {
            int kg = (kt + 1) * 32;
#pragma unroll
            for (int it = 0; it < 4; it++) {
                a4[it] = *(const float4*)(Ab + (size_t)rr[it] * K + kg + ko4[it]);
                b4[it] = *(const float4*)(Bb + (size_t)rr[it] * K + kg + ko4[it]);
            }
        }

#pragma unroll
        for (int k8 = 0; k8 < 4; k8++) {
            const int co = k8 * CHUNK;
            uint2 af[4][2], bf[4];
#pragma unroll
            for (int mt = 0; mt < 4; mt++) {
                const float* p = &As[co + (warp_m * 64 + mt * 16 + g) * 8 + 2 * t];
                af[mt][0] = *(const uint2*)p;
                af[mt][1] = *(const uint2*)(p + 64);
            }
#pragma unroll
            for (int nt = 0; nt < 4; nt++)
                bf[nt] = *(const uint2*)&Bs[co + (warp_n * 32 + nt * 8 + g) * 8 + 2 * t];
#pragma unroll
            for (int mt = 0; mt < 4; mt++)
#pragma unroll
                for (int nt = 0; nt < 4; nt++)
                    mma_tf32(acc[mt][nt], af[mt][0], af[mt][1], bf[nt]);
        }
    }

#pragma unroll
    for (int mt = 0; mt < 4; mt++) {
        int row = bm + warp_m * 64 + mt * 16 + g;
#pragma unroll
        for (int nt = 0; nt < 4; nt++) {
            int col = bn + warp_n * 32 + nt * 8 + 2 * t;
            float b0 = 0.f, b1 = 0.f;
            if (bias) { b0 = bias[col]; b1 = bias[col + 1]; }
            float2 v0 = make_float2(acc[mt][nt][0] + b0, acc[mt][nt][1] + b1);
            float2 v1 = make_float2(acc[mt][nt][2] + b0, acc[mt][nt][3] + b1);
            *(float2*)(C + (size_t)row * N + col)       = v0;
            *(float2*)(C + (size_t)(row + 8) * N + col) = v1;
        }
    }
}

__global__ void __launch_bounds__(256) qkv_gemm_kernel(
    const float* __restrict__ X,
    const float* __restrict__ Wq,
    const float* __restrict__ Wk,
    const float* __restrict__ Wv)
{
    const float* B = (blockIdx.z == 0) ? Wq : (blockIdx.z == 1) ? Wk : Wv;
    float* C       = (blockIdx.z == 0) ? g_Q : (blockIdx.z == 1) ? g_K : g_V;
    mma_gemm_body(X, B, nullptr, C, HDIM, HDIM);
}

__global__ void __launch_bounds__(256) out_gemm_kernel(
    const float* __restrict__ Wo,
    const float* __restrict__ bo,
    float* __restrict__ out)
{
    mma_gemm_body(g_C, Wo, bo, out, HDIM, HDIM);
}

// ---------------------------------------------------------------------------
// RoPE in-place on g_Q, g_K
// ---------------------------------------------------------------------------
__global__ void rope_kernel(const int* __restrict__ pos_ids)
{
    int idx = blockIdx.x * 256 + threadIdx.x;
    if (idx >= MROWS * NH * 64) return;
    int d = idx & 63;
    int h = (idx >> 6) & 15;
    int m = idx >> 10;
    int s = m & (S_LEN - 1);

    float p = (float)pos_ids[s];
    float theta = expf(-0.14391156531392624f * (float)d);
    float ang = p * theta;
    float sn, cs;
    sincosf(ang, &sn, &cs);

    size_t base = (size_t)m * HDIM + h * DH + d;
    float q1 = g_Q[base], q2 = g_Q[base + 64];
    g_Q[base]      = q1 * cs - q2 * sn;
    g_Q[base + 64] = q1 * sn + q2 * cs;
    float k1 = g_K[base], k2 = g_K[base + 64];
    g_K[base]      = k1 * cs - k2 * sn;
    g_K[base + 64] = k1 * sn + k2 * cs;
}

// ---------------------------------------------------------------------------
// TF32 MMA flash attention. CTA: 128 q-rows x 64 k-tile, dh=128, 8 warps.
// Warp w owns q rows [w*16, w*16+16): softmax stats reduce within quads only.
// Q: 16 k8-chunks of [128][8] k-permuted (CQ=1034).
// K: 16 k8-chunks of [64][8]  k-permuted (CK=522).
// V: plain [64][132]; P-as-A col order sigma(j) makes b-frags rows {2t,2t+1}.
// ---------------------------------------------------------------------------
#define CQ 1034
#define CK 522
#define VSTRIDE 132
#define ATT_SMEM_FLOATS (16 * CQ + 16 * CK + 64 * VSTRIDE)
#define ATT_SMEM_BYTES  (ATT_SMEM_FLOATS * 4)

__global__ void __launch_bounds__(256) attn_kernel()
{
    extern __shared__ float sm[];
    float* Qs = sm;
    float* Ks = Qs + 16 * CQ;
    float* Vs = Ks + 16 * CK;

    const int tid  = threadIdx.x;
    const int lane = tid & 31;
    const int w    = tid >> 5;
    const int g    = lane >> 2;
    const int t    = lane & 3;
    const int qt   = (gridDim.x - 1) - blockIdx.x;   // heavy tiles first
    const int h    = blockIdx.y;
    const int n    = blockIdx.z;
    const int q0   = qt * 128;
    const float rs = 0.08838834764831845f;   // 1/sqrt(128)

    const size_t rowbase = (size_t)n * S_LEN;
    const size_t hoff    = (size_t)h * DH;

    // Load Q tile (pre-scaled, tf32, k-permuted)
#pragma unroll
    for (int it = 0; it < 16; it++) {
        int id = tid + it * 256;
        int r  = id >> 5;
        int f4 = id & 31;
        int so = (f4 >> 1) * CQ + r * 8 + (f4 & 1);
        float4 v = *(const float4*)(g_Q + (rowbase + q0 + r) * HDIM + hoff + f4 * 4);
        Qs[so + 0] = f2tf32(v.x * rs);
        Qs[so + 2] = f2tf32(v.y * rs);
        Qs[so + 4] = f2tf32(v.z * rs);
        Qs[so + 6] = f2tf32(v.w * rs);
    }

    float o[16][4];
#pragma unroll
    for (int dd = 0; dd < 16; dd++)
#pragma unroll
        for (int i = 0; i < 4; i++) o[dd][i] = 0.f;
    float m0 = -1e30f, m1 = -1e30f, l0 = 0.f, l1 = 0.f;

    const int row0 = q0 + w * 16 + g;      // global q row (thread's even row)
    const int nkt  = 2 * (qt + 1);

    for (int kt = 0; kt < nkt; kt++) {
        __syncthreads();
        const int k0 = kt * 64;
#pragma unroll
        for (int it = 0; it < 8; it++) {
            int id = tid + it * 256;
            int r  = id >> 5;
            int f4 = id & 31;
            size_t gg = (rowbase + k0 + r) * HDIM + hoff + f4 * 4;
            float4 vk = *(const float4*)(g_K + gg);
            int so = (f4 >> 1) * CK + r * 8 + (f4 & 1);
            Ks[so + 0] = f2tf32(vk.x);
            Ks[so + 2] = f2tf32(vk.y);
            Ks[so + 4] = f2tf32(vk.z);
            Ks[so + 6] = f2tf32(vk.w);
            float4 vv = *(const float4*)(g_V + gg);
            vv.x = f2tf32(vv.x); vv.y = f2tf32(vv.y);
            vv.z = f2tf32(vv.z); vv.w = f2tf32(vv.w);
            *(float4*)&Vs[r * VSTRIDE + f4 * 4] = vv;
        }
        __syncthreads();

        // ---- S = Q K^T ----
        float s[8][4];
#pragma unroll
        for (int nn = 0; nn < 8; nn++)
#pragma unroll
            for (int i = 0; i < 4; i++) s[nn][i] = 0.f;

#pragma unroll
        for (int c = 0; c < 16; c++) {
            const float* qp = &Qs[c * CQ + (w * 16 + g) * 8 + 2 * t];
            uint2 alo = *(const uint2*)qp;
            uint2 ahi = *(const uint2*)(qp + 64);
#pragma unroll
            for (int nn = 0; nn < 8; nn++) {
                uint2 b = *(const uint2*)&Ks[c * CK + (nn * 8 + g) * 8 + 2 * t];
                mma_tf32(s[nn], alo, ahi, b);
            }
        }

        // ---- causal mask (only near diagonal) ----
        if (k0 + 63 > row0) {
#pragma unroll
            for (int nn = 0; nn < 8; nn++) {
                int col = k0 + nn * 8 + 2 * t;
                if (col > row0)     s[nn][0] = -1e30f;
                if (col + 1 > row0) s[nn][1] = -1e30f;
                if (col > row0 + 8)     s[nn][2] = -1e30f;
                if (col + 1 > row0 + 8) s[nn][3] = -1e30f;
            }
        }

        // ---- online softmax (register-resident, quad reductions) ----
        float mx0 = -1e30f, mx1 = -1e30f;
#pragma unroll
        for (int nn = 0; nn < 8; nn++) {
            mx0 = fmaxf(mx0, fmaxf(s[nn][0], s[nn][1]));
            mx1 = fmaxf(mx1, fmaxf(s[nn][2], s[nn][3]));
        }
        mx0 = fmaxf(mx0, __shfl_xor_sync(0xffffffffu, mx0, 1));
        mx0 = fmaxf(mx0, __shfl_xor_sync(0xffffffffu, mx0, 2));
        mx1 = fmaxf(mx1, __shfl_xor_sync(0xffffffffu, mx1, 1));
        mx1 = fmaxf(mx1, __shfl_xor_sync(0xffffffffu, mx1, 2));

        float newm0 = fmaxf(m0, mx0);
        float newm1 = fmaxf(m1, mx1);
        float alpha0 = __expf(m0 - newm0);
        float alpha1 = __expf(m1 - newm1);
        m0 = newm0; m1 = newm1;

        float sum0 = 0.f, sum1 = 0.f;
#pragma unroll
        for (int nn = 0; nn < 8; nn++) {
            float p0 = f2tf32(__expf(s[nn][0] - newm0));
            float p1 = f2tf32(__expf(s[nn][1] - newm0));
            float p2 = f2tf32(__expf(s[nn][2] - newm1));
            float p3 = f2tf32(__expf(s[nn][3] - newm1));
            s[nn][0] = p0; s[nn][1] = p1; s[nn][2] = p2; s[nn][3] = p3;
            sum0 += p0 + p1;
            sum1 += p2 + p3;
        }
        sum0 += __shfl_xor_sync(0xffffffffu, sum0, 1);
        sum0 += __shfl_xor_sync(0xffffffffu, sum0, 2);
        sum1 += __shfl_xor_sync(0xffffffffu, sum1, 1);
        sum1 += __shfl_xor_sync(0xffffffffu, sum1, 2);
        l0 = l0 * alpha0 + sum0;
        l1 = l1 * alpha1 + sum1;

#pragma unroll
        for (int dd = 0; dd < 16; dd++) {
            o[dd][0] *= alpha0; o[dd][1] *= alpha0;
            o[dd][2] *= alpha1; o[dd][3] *= alpha1;
        }

        // ---- O += P V : P c-frags reused directly as a-frags ----
#pragma unroll
        for (int c8 = 0; c8 < 8; c8++) {
            const float* vp = &Vs[(c8 * 8 + 2 * t) * VSTRIDE + g];
#pragma unroll
            for (int dd = 0; dd < 16; dd++) {
                float b0 = vp[dd * 8];
                float b1 = vp[dd * 8 + VSTRIDE];
                mma_tf32_r(o[dd], s[c8][0], s[c8][2], s[c8][1], s[c8][3], b0, b1);
            }
        }
    }

    // ---- epilogue ----
    float inv0 = 1.f / l0;
    float inv1 = 1.f / l1;
    size_t r0 = (rowbase + row0) * HDIM + hoff;
    size_t r1 = r0 + 8 * HDIM;
#pragma unroll
    for (int dd = 0; dd < 16; dd++) {
        int col = dd * 8 + 2 * t;
        *(float2*)(g_C + r0 + col) = make_float2(o[dd][0] * inv0, o[dd][1] * inv0);
        *(float2*)(g_C + r1 + col) = make_float2(o[dd][2] * inv1, o[dd][3] * inv1);
    }
}

// ---------------------------------------------------------------------------
// kernel_launch
// Inputs: 0=X 1=position_ids 2=mask(unused,causal) 3=Wq 4=Wk 5=Wv 6=Wo 7=bo
// ---------------------------------------------------------------------------
extern "C" void kernel_launch(void* const* d_in, const int* in_sizes, int n_in,
                              void* d_out, int out_size)
{
    const float* X   = (const float*)d_in[0];
    const int*   pos = (const int*)d_in[1];
    const float* Wq  = (const float*)d_in[3];
    const float* Wk  = (const float*)d_in[4];
    const float* Wv  = (const float*)d_in[5];
    const float* Wo  = (const float*)d_in[6];
    const float* bo  = (const float*)d_in[7];
    float* out = (float*)d_out;

    cudaFuncSetAttribute(attn_kernel,
                         cudaFuncAttributeMaxDynamicSharedMemorySize,
                         ATT_SMEM_BYTES);

    dim3 g_qkv(HDIM / 128, MROWS / 128, 3);
    qkv_gemm_kernel<<<g_qkv, 256>>>(X, Wq, Wk, Wv);

    int rope_threads = MROWS * NH * 64;
    rope_kernel<<<(rope_threads + 255) / 256, 256>>>(pos);

    dim3 g_att(S_LEN / 128, NH, NB);
    attn_kernel<<<g_att, 256, ATT_SMEM_BYTES>>>();

    dim3 g_out(HDIM / 128, MROWS / 128);
    out_gemm_kernel<<<g_out, 256>>>(Wo, bo, out);
}

// round 4
// speedup vs baseline: 3.9707x; 1.2358x over previous
#include <cuda_runtime.h>
#include <math.h>
#include <stdint.h>

#define S_LEN 2048
#define HDIM  2048
#define NB    2
#define NH    16
#define DH    128
#define MROWS (NB * S_LEN)   // 4096

__device__ float g_Q[MROWS * HDIM];
__device__ float g_K[MROWS * HDIM];
__device__ float g_V[MROWS * HDIM];
__device__ float g_C[MROWS * HDIM];

// ---------------------------------------------------------------------------
// TF32 helpers
// ---------------------------------------------------------------------------
__device__ __forceinline__ float f2tf32(float x)
{
    unsigned u;
    asm("cvt.rna.tf32.f32 %0, %1;" : "=r"(u) : "f"(x));
    return __uint_as_float(u);
}

// D += A(m16k8,row) * B(k8n8,col) tf32, fp32 accum.
// a0=(g,t) a1=(g+8,t) a2=(g,t+4) a3=(g+8,t+4); b0=(t,g) b1=(t+4,g)
__device__ __forceinline__ void mma_tf32(float* c, uint2 alo, uint2 ahi, uint2 b)
{
    asm("mma.sync.aligned.m16n8k8.row.col.f32.tf32.tf32.f32 "
        "{%0,%1,%2,%3}, {%4,%5,%6,%7}, {%8,%9}, {%0,%1,%2,%3};"
        : "+f"(c[0]), "+f"(c[1]), "+f"(c[2]), "+f"(c[3])
        : "r"(alo.x), "r"(ahi.x), "r"(alo.y), "r"(ahi.y),
          "r"(b.x),  "r"(b.y));
}

__device__ __forceinline__ void mma_tf32_r(float* c, float a0, float a1,
                                           float a2, float a3,
                                           float b0, float b1)
{
    asm("mma.sync.aligned.m16n8k8.row.col.f32.tf32.tf32.f32 "
        "{%0,%1,%2,%3}, {%4,%5,%6,%7}, {%8,%9}, {%0,%1,%2,%3};"
        : "+f"(c[0]), "+f"(c[1]), "+f"(c[2]), "+f"(c[3])
        : "r"(__float_as_uint(a0)), "r"(__float_as_uint(a1)),
          "r"(__float_as_uint(a2)), "r"(__float_as_uint(a3)),
          "r"(__float_as_uint(b0)), "r"(__float_as_uint(b1)));
}

__device__ __forceinline__ void cp_async16(uint32_t saddr, const float* g)
{
    asm volatile("cp.async.cg.shared.global [%0], [%1], 16;"
                 :: "r"(saddr), "l"(g));
}
#define CP_COMMIT() asm volatile("cp.async.commit_group;")
#define CP_WAIT(N)  asm volatile("cp.async.wait_group %0;" :: "n"(N))

// ---------------------------------------------------------------------------
// GEMM v2: C[M,2048] = A[M,2048] @ B[2048,2048]^T (+bias).
// CTA 128x128, 128 threads = 4 warps (2m x 2n), warp tile 64x64, BK=32.
// 3-stage cp.async pipeline, raw fp32 in smem, cvt.rna at fragment load.
// Smem layout: [row][8 float4-chunks], chunk j stored at j ^ (row&7).
// All fragment rows are ( multiple of 8 ) + g, so row&7 == g for frag loads.
// ---------------------------------------------------------------------------
#define GK 2048
#define TILE_F 4096              // 128 rows * 32 floats
#define GEMM_SMEM_BYTES (3 * TILE_F * 2 * 4)   // 96 KB

__device__ __forceinline__ void gemm_v2_body(const float* __restrict__ A,
                                             const float* __restrict__ B,
                                             const float* __restrict__ bias,
                                             float* __restrict__ C)
{
    extern __shared__ float smem[];
    float* As = smem;                 // [3][4096]
    float* Bs = smem + 3 * TILE_F;    // [3][4096]

    const int tid    = threadIdx.x;
    const int lane   = tid & 31;
    const int wid    = tid >> 5;
    const int warp_m = wid >> 1;      // 0..1
    const int warp_n = wid & 1;       // 0..1
    const int g      = lane >> 2;     // 0..7
    const int t      = lane & 3;      // 0..3
    const int bm     = blockIdx.y * 128;
    const int bn     = blockIdx.x * 128;

    // cp.async source/dest: thread covers rows (tid>>3) + 16*it, chunk tid&7
    const int ld_row0  = tid >> 3;
    const int ld_chunk = tid & 7;
    const float* gA = A + (size_t)(bm + ld_row0) * GK + ld_chunk * 4;
    const float* gB = B + (size_t)(bn + ld_row0) * GK + ld_chunk * 4;
    const int dst0 = ld_row0 * 32 + ((ld_chunk ^ (ld_row0 & 7)) << 2);

    uint32_t sA = (uint32_t)__cvta_generic_to_shared(As);
    uint32_t sB = (uint32_t)__cvta_generic_to_shared(Bs);

    // issue stage: 8 A + 8 B cp.async of 16B each
    auto issue = [&](int stage) {
        uint32_t da = sA + (stage * TILE_F + dst0) * 4;
        uint32_t db = sB + (stage * TILE_F + dst0) * 4;
#pragma unroll
        for (int it = 0; it < 8; it++)
            cp_async16(da + it * 512 * 4, gA + (size_t)it * 16 * GK);
#pragma unroll
        for (int it = 0; it < 8; it++)
            cp_async16(db + it * 512 * 4, gB + (size_t)it * 16 * GK);
        gA += 32;
        gB += 32;
        CP_COMMIT();
    };

    issue(0);
    issue(1);

    float acc[4][8][4];
#pragma unroll
    for (int mt = 0; mt < 4; mt++)
#pragma unroll
        for (int nt = 0; nt < 8; nt++)
#pragma unroll
            for (int i = 0; i < 4; i++) acc[mt][nt][i] = 0.f;

    // fragment row bases (float index into a tile)
    int rbA[4], rbB[8];
#pragma unroll
    for (int mt = 0; mt < 4; mt++)
        rbA[mt] = (warp_m * 64 + mt * 16 + g) * 32;
#pragma unroll
    for (int nt = 0; nt < 8; nt++)
        rbB[nt] = (warp_n * 64 + nt * 8 + g) * 32;

    const int nk = GK / 32;   // 64
    for (int kt = 0; kt < nk; kt++) {
        if (kt < nk - 1) { CP_WAIT(1); } else { CP_WAIT(0); }
        __syncthreads();
        if (kt + 2 < nk) issue((kt + 2) % 3);

        const float* as = As + (kt % 3) * TILE_F;
        const float* bs = Bs + (kt % 3) * TILE_F;

#pragma unroll
        for (int k8 = 0; k8 < 4; k8++) {
            const int o0 = (((2 * k8)     ^ g) << 2) + t;
            const int o1 = (((2 * k8 + 1) ^ g) << 2) + t;

            float a[4][4];
#pragma unroll
            for (int mt = 0; mt < 4; mt++) {
                a[mt][0] = f2tf32(as[rbA[mt] + o0]);
                a[mt][1] = f2tf32(as[rbA[mt] + 256 + o0]);
                a[mt][2] = f2tf32(as[rbA[mt] + o1]);
                a[mt][3] = f2tf32(as[rbA[mt] + 256 + o1]);
            }
            float b[8][2];
#pragma unroll
            for (int nt = 0; nt < 8; nt++) {
                b[nt][0] = f2tf32(bs[rbB[nt] + o0]);
                b[nt][1] = f2tf32(bs[rbB[nt] + o1]);
            }
#pragma unroll
            for (int mt = 0; mt < 4; mt++)
#pragma unroll
                for (int nt = 0; nt < 8; nt++)
                    mma_tf32_r(acc[mt][nt],
                               a[mt][0], a[mt][1], a[mt][2], a[mt][3],
                               b[nt][0], b[nt][1]);
        }
    }

    // Epilogue: c0,c1 at (g, 2t..2t+1); c2,c3 at (g+8, ...)
#pragma unroll
    for (int mt = 0; mt < 4; mt++) {
        int row = bm + warp_m * 64 + mt * 16 + g;
#pragma unroll
        for (int nt = 0; nt < 8; nt++) {
            int col = bn + warp_n * 64 + nt * 8 + 2 * t;
            float b0 = 0.f, b1 = 0.f;
            if (bias) { b0 = bias[col]; b1 = bias[col + 1]; }
            *(float2*)(C + (size_t)row * HDIM + col) =
                make_float2(acc[mt][nt][0] + b0, acc[mt][nt][1] + b1);
            *(float2*)(C + (size_t)(row + 8) * HDIM + col) =
                make_float2(acc[mt][nt][2] + b0, acc[mt][nt][3] + b1);
        }
    }
}

__global__ void __launch_bounds__(128, 2) qkv_gemm_kernel(
    const float* __restrict__ X,
    const float* __restrict__ Wq,
    const float* __restrict__ Wk,
    const float* __restrict__ Wv)
{
    const float* B = (blockIdx.z == 0) ? Wq : (blockIdx.z == 1) ? Wk : Wv;
    float* C       = (blockIdx.z == 0) ? g_Q : (blockIdx.z == 1) ? g_K : g_V;
    gemm_v2_body(X, B, nullptr, C);
}

__global__ void __launch_bounds__(128, 2) out_gemm_kernel(
    const float* __restrict__ Wo,
    const float* __restrict__ bo,
    float* __restrict__ out)
{
    gemm_v2_body(g_C, Wo, bo, out);
}

// ---------------------------------------------------------------------------
// RoPE in-place on g_Q, g_K
// ---------------------------------------------------------------------------
__global__ void rope_kernel(const int* __restrict__ pos_ids)
{
    int idx = blockIdx.x * 256 + threadIdx.x;
    if (idx >= MROWS * NH * 64) return;
    int d = idx & 63;
    int h = (idx >> 6) & 15;
    int m = idx >> 10;
    int s = m & (S_LEN - 1);

    float p = (float)pos_ids[s];
    float theta = expf(-0.14391156531392624f * (float)d);
    float ang = p * theta;
    float sn, cs;
    sincosf(ang, &sn, &cs);

    size_t base = (size_t)m * HDIM + h * DH + d;
    float q1 = g_Q[base], q2 = g_Q[base + 64];
    g_Q[base]      = q1 * cs - q2 * sn;
    g_Q[base + 64] = q1 * sn + q2 * cs;
    float k1 = g_K[base], k2 = g_K[base + 64];
    g_K[base]      = k1 * cs - k2 * sn;
    g_K[base + 64] = k1 * sn + k2 * cs;
}

// ---------------------------------------------------------------------------
// TF32 MMA flash attention (unchanged from R3).
// ---------------------------------------------------------------------------
#define CQ 1034
#define CK 522
#define VSTRIDE 132
#define ATT_SMEM_FLOATS (16 * CQ + 16 * CK + 64 * VSTRIDE)
#define ATT_SMEM_BYTES  (ATT_SMEM_FLOATS * 4)

__global__ void __launch_bounds__(256) attn_kernel()
{
    extern __shared__ float sm[];
    float* Qs = sm;
    float* Ks = Qs + 16 * CQ;
    float* Vs = Ks + 16 * CK;

    const int tid  = threadIdx.x;
    const int lane = tid & 31;
    const int w    = tid >> 5;
    const int g    = lane >> 2;
    const int t    = lane & 3;
    const int qt   = (gridDim.x - 1) - blockIdx.x;
    const int h    = blockIdx.y;
    const int n    = blockIdx.z;
    const int q0   = qt * 128;
    const float rs = 0.08838834764831845f;

    const size_t rowbase = (size_t)n * S_LEN;
    const size_t hoff    = (size_t)h * DH;

#pragma unroll
    for (int it = 0; it < 16; it++) {
        int id = tid + it * 256;
        int r  = id >> 5;
        int f4 = id & 31;
        int so = (f4 >> 1) * CQ + r * 8 + (f4 & 1);
        float4 v = *(const float4*)(g_Q + (rowbase + q0 + r) * HDIM + hoff + f4 * 4);
        Qs[so + 0] = f2tf32(v.x * rs);
        Qs[so + 2] = f2tf32(v.y * rs);
        Qs[so + 4] = f2tf32(v.z * rs);
        Qs[so + 6] = f2tf32(v.w * rs);
    }

    float o[16][4];
#pragma unroll
    for (int dd = 0; dd < 16; dd++)
#pragma unroll
        for (int i = 0; i < 4; i++) o[dd][i] = 0.f;
    float m0 = -1e30f, m1 = -1e30f, l0 = 0.f, l1 = 0.f;

    const int row0 = q0 + w * 16 + g;
    const int nkt  = 2 * (qt + 1);

    for (int kt = 0; kt < nkt; kt++) {
        __syncthreads();
        const int k0 = kt * 64;
#pragma unroll
        for (int it = 0; it < 8; it++) {
            int id = tid + it * 256;
            int r  = id >> 5;
            int f4 = id & 31;
            size_t gg = (rowbase + k0 + r) * HDIM + hoff + f4 * 4;
            float4 vk = *(const float4*)(g_K + gg);
            int so = (f4 >> 1) * CK + r * 8 + (f4 & 1);
            Ks[so + 0] = f2tf32(vk.x);
            Ks[so + 2] = f2tf32(vk.y);
            Ks[so + 4] = f2tf32(vk.z);
            Ks[so + 6] = f2tf32(vk.w);
            float4 vv = *(const float4*)(g_V + gg);
            vv.x = f2tf32(vv.x); vv.y = f2tf32(vv.y);
            vv.z = f2tf32(vv.z); vv.w = f2tf32(vv.w);
            *(float4*)&Vs[r * VSTRIDE + f4 * 4] = vv;
        }
        __syncthreads();

        float s[8][4];
#pragma unroll
        for (int nn = 0; nn < 8; nn++)
#pragma unroll
            for (int i = 0; i < 4; i++) s[nn][i] = 0.f;

#pragma unroll
        for (int c = 0; c < 16; c++) {
            const float* qp = &Qs[c * CQ + (w * 16 + g) * 8 + 2 * t];
            uint2 alo = *(const uint2*)qp;
            uint2 ahi = *(const uint2*)(qp + 64);
#pragma unroll
            for (int nn = 0; nn < 8; nn++) {
                uint2 b = *(const uint2*)&Ks[c * CK + (nn * 8 + g) * 8 + 2 * t];
                mma_tf32(s[nn], alo, ahi, b);
            }
        }

        if (k0 + 63 > row0) {
#pragma unroll
            for (int nn = 0; nn < 8; nn++) {
                int col = k0 + nn * 8 + 2 * t;
                if (col > row0)     s[nn][0] = -1e30f;
                if (col + 1 > row0) s[nn][1] = -1e30f;
                if (col > row0 + 8)     s[nn][2] = -1e30f;
                if (col + 1 > row0 + 8) s[nn][3] = -1e30f;
            }
        }

        float mx0 = -1e30f, mx1 = -1e30f;
#pragma unroll
        for (int nn = 0; nn < 8; nn++) {
            mx0 = fmaxf(mx0, fmaxf(s[nn][0], s[nn][1]));
            mx1 = fmaxf(mx1, fmaxf(s[nn][2], s[nn][3]));
        }
        mx0 = fmaxf(mx0, __shfl_xor_sync(0xffffffffu, mx0, 1));
        mx0 = fmaxf(mx0, __shfl_xor_sync(0xffffffffu, mx0, 2));
        mx1 = fmaxf(mx1, __shfl_xor_sync(0xffffffffu, mx1, 1));
        mx1 = fmaxf(mx1, __shfl_xor_sync(0xffffffffu, mx1, 2));

        float newm0 = fmaxf(m0, mx0);
        float newm1 = fmaxf(m1, mx1);
        float alpha0 = __expf(m0 - newm0);
        float alpha1 = __expf(m1 - newm1);
        m0 = newm0; m1 = newm1;

        float sum0 = 0.f, sum1 = 0.f;
#pragma unroll
        for (int nn = 0; nn < 8; nn++) {
            float p0 = f2tf32(__expf(s[nn][0] - newm0));
            float p1 = f2tf32(__expf(s[nn][1] - newm0));
            float p2 = f2tf32(__expf(s[nn][2] - newm1));
            float p3 = f2tf32(__expf(s[nn][3] - newm1));
            s[nn][0] = p0; s[nn][1] = p1; s[nn][2] = p2; s[nn][3] = p3;
            sum0 += p0 + p1;
            sum1 += p2 + p3;
        }
        sum0 += __shfl_xor_sync(0xffffffffu, sum0, 1);
        sum0 += __shfl_xor_sync(0xffffffffu, sum0, 2);
        sum1 += __shfl_xor_sync(0xffffffffu, sum1, 1);
        sum1 += __shfl_xor_sync(0xffffffffu, sum1, 2);
        l0 = l0 * alpha0 + sum0;
        l1 = l1 * alpha1 + sum1;

#pragma unroll
        for (int dd = 0; dd < 16; dd++) {
            o[dd][0] *= alpha0; o[dd][1] *= alpha0;
            o[dd][2] *= alpha1; o[dd][3] *= alpha1;
        }

#pragma unroll
        for (int c8 = 0; c8 < 8; c8++) {
            const float* vp = &Vs[(c8 * 8 + 2 * t) * VSTRIDE + g];
#pragma unroll
            for (int dd = 0; dd < 16; dd++) {
                float b0 = vp[dd * 8];
                float b1 = vp[dd * 8 + VSTRIDE];
                mma_tf32_r(o[dd], s[c8][0], s[c8][2], s[c8][1], s[c8][3], b0, b1);
            }
        }
    }

    float inv0 = 1.f / l0;
    float inv1 = 1.f / l1;
    size_t r0 = (rowbase + row0) * HDIM + hoff;
    size_t r1 = r0 + 8 * HDIM;
#pragma unroll
    for (int dd = 0; dd < 16; dd++) {
        int col = dd * 8 + 2 * t;
        *(float2*)(g_C + r0 + col) = make_float2(o[dd][0] * inv0, o[dd][1] * inv0);
        *(float2*)(g_C + r1 + col) = make_float2(o[dd][2] * inv1, o[dd][3] * inv1);
    }
}

// ---------------------------------------------------------------------------
// kernel_launch
// Inputs: 0=X 1=position_ids 2=mask(unused,causal) 3=Wq 4=Wk 5=Wv 6=Wo 7=bo
// ---------------------------------------------------------------------------
extern "C" void kernel_launch(void* const* d_in, const int* in_sizes, int n_in,
                              void* d_out, int out_size)
{
    const float* X   = (const float*)d_in[0];
    const int*   pos = (const int*)d_in[1];
    const float* Wq  = (const float*)d_in[3];
    const float* Wk  = (const float*)d_in[4];
    const float* Wv  = (const float*)d_in[5];
    const float* Wo  = (const float*)d_in[6];
    const float* bo  = (const float*)d_in[7];
    float* out = (float*)d_out;

    cudaFuncSetAttribute(qkv_gemm_kernel,
                         cudaFuncAttributeMaxDynamicSharedMemorySize,
                         GEMM_SMEM_BYTES);
    cudaFuncSetAttribute(out_gemm_kernel,
                         cudaFuncAttributeMaxDynamicSharedMemorySize,
                         GEMM_SMEM_BYTES);
    cudaFuncSetAttribute(attn_kernel,
                         cudaFuncAttributeMaxDynamicSharedMemorySize,
                         ATT_SMEM_BYTES);

    dim3 g_qkv(HDIM / 128, MROWS / 128, 3);
    qkv_gemm_kernel<<<g_qkv, 128, GEMM_SMEM_BYTES>>>(X, Wq, Wk, Wv);

    int rope_threads = MROWS * NH * 64;
    rope_kernel<<<(rope_threads + 255) / 256, 256>>>(pos);

    dim3 g_att(S_LEN / 128, NH, NB);
    attn_kernel<<<g_att, 256, ATT_SMEM_BYTES>>>();

    dim3 g_out(HDIM / 128, MROWS / 128);
    out_gemm_kernel<<<g_out, 128, GEMM_SMEM_BYTES>>>(Wo, bo, out);
}

// round 5
// speedup vs baseline: 4.1149x; 1.0363x over previous
#include <cuda_runtime.h>
#include <math.h>
#include <stdint.h>

#define S_LEN 2048
#define HDIM  2048
#define NB    2
#define NH    16
#define DH    128
#define MROWS (NB * S_LEN)   // 4096

__device__ float g_Q[MROWS * HDIM];
__device__ float g_K[MROWS * HDIM];
__device__ float g_V[MROWS * HDIM];
__device__ float g_C[MROWS * HDIM];
__device__ float g_X[MROWS * HDIM];          // tf32-rounded X
__device__ float g_Wq[HDIM * HDIM];          // tf32-rounded, pre-scaled by 1/sqrt(dh)
__device__ float g_Wk[HDIM * HDIM];
__device__ float g_Wv[HDIM * HDIM];
__device__ float g_Wo[HDIM * HDIM];

// ---------------------------------------------------------------------------
// TF32 helpers
// ---------------------------------------------------------------------------
__device__ __forceinline__ float f2tf32(float x)
{
    unsigned u;
    asm("cvt.rna.tf32.f32 %0, %1;" : "=r"(u) : "f"(x));
    return __uint_as_float(u);
}

// D += A(m16k8,row) * B(k8n8,col) tf32, fp32 accum.
__device__ __forceinline__ void mma_tf32(float* c, uint2 alo, uint2 ahi, uint2 b)
{
    asm("mma.sync.aligned.m16n8k8.row.col.f32.tf32.tf32.f32 "
        "{%0,%1,%2,%3}, {%4,%5,%6,%7}, {%8,%9}, {%0,%1,%2,%3};"
        : "+f"(c[0]), "+f"(c[1]), "+f"(c[2]), "+f"(c[3])
        : "r"(alo.x), "r"(ahi.x), "r"(alo.y), "r"(ahi.y),
          "r"(b.x),  "r"(b.y));
}

__device__ __forceinline__ void mma_tf32_r(float* c, float a0, float a1,
                                           float a2, float a3,
                                           float b0, float b1)
{
    asm("mma.sync.aligned.m16n8k8.row.col.f32.tf32.tf32.f32 "
        "{%0,%1,%2,%3}, {%4,%5,%6,%7}, {%8,%9}, {%0,%1,%2,%3};"
        : "+f"(c[0]), "+f"(c[1]), "+f"(c[2]), "+f"(c[3])
        : "r"(__float_as_uint(a0)), "r"(__float_as_uint(a1)),
          "r"(__float_as_uint(a2)), "r"(__float_as_uint(a3)),
          "r"(__float_as_uint(b0)), "r"(__float_as_uint(b1)));
}

__device__ __forceinline__ void cp_async16(uint32_t saddr, const float* g)
{
    asm volatile("cp.async.cg.shared.global [%0], [%1], 16;"
                 :: "r"(saddr), "l"(g));
}
#define CP_COMMIT() asm volatile("cp.async.commit_group;")
#define CP_WAIT(N)  asm volatile("cp.async.wait_group %0;" :: "n"(N))

// ---------------------------------------------------------------------------
// tf32 pre-rounding copy kernel (optionally scaled)
// ---------------------------------------------------------------------------
__global__ void cvt_tf32_kernel(const float* __restrict__ src,
                                float* __restrict__ dst,
                                int n4, float scale)
{
    int i = blockIdx.x * 256 + threadIdx.x;
    if (i >= n4) return;
    float4 v = ((const float4*)src)[i];
    v.x = f2tf32(v.x * scale);
    v.y = f2tf32(v.y * scale);
    v.z = f2tf32(v.z * scale);
    v.w = f2tf32(v.w * scale);
    ((float4*)dst)[i] = v;
}

// ---------------------------------------------------------------------------
// GEMM v3: C[M,2048] = A[M,2048] @ B[2048,2048]^T (+bias).
// CTA 128x128, 128 threads = 4 warps (2m x 2n), warp tile 64x64, BK=32.
// 3-stage cp.async pipeline. All operands PRE-ROUNDED to tf32 -> no cvt
// in the mainloop; raw bits go straight into mma.sync.
// Smem: [row][8 float4-chunks], chunk j at j ^ (row&7).
// ---------------------------------------------------------------------------
#define GK 2048
#define TILE_F 4096              // 128 rows * 32 floats
#define GEMM_SMEM_BYTES (3 * TILE_F * 2 * 4)   // 96 KB

template <bool ROUND>
__device__ __forceinline__ void gemm_v3_body(const float* __restrict__ A,
                                             const float* __restrict__ B,
                                             const float* __restrict__ bias,
                                             float* __restrict__ C)
{
    extern __shared__ float smem[];
    float* As = smem;
    float* Bs = smem + 3 * TILE_F;

    const int tid    = threadIdx.x;
    const int lane   = tid & 31;
    const int wid    = tid >> 5;
    const int warp_m = wid >> 1;
    const int warp_n = wid & 1;
    const int g      = lane >> 2;
    const int t      = lane & 3;
    const int bm     = blockIdx.y * 128;
    const int bn     = blockIdx.x * 128;

    const int ld_row0  = tid >> 3;
    const int ld_chunk = tid & 7;
    const float* gA = A + (size_t)(bm + ld_row0) * GK + ld_chunk * 4;
    const float* gB = B + (size_t)(bn + ld_row0) * GK + ld_chunk * 4;
    const int dst0 = ld_row0 * 32 + ((ld_chunk ^ (ld_row0 & 7)) << 2);

    uint32_t sA = (uint32_t)__cvta_generic_to_shared(As);
    uint32_t sB = (uint32_t)__cvta_generic_to_shared(Bs);

    auto issue = [&](int stage) {
        uint32_t da = sA + (stage * TILE_F + dst0) * 4;
        uint32_t db = sB + (stage * TILE_F + dst0) * 4;
#pragma unroll
        for (int it = 0; it < 8; it++)
            cp_async16(da + it * 512 * 4, gA + (size_t)it * 16 * GK);
#pragma unroll
        for (int it = 0; it < 8; it++)
            cp_async16(db + it * 512 * 4, gB + (size_t)it * 16 * GK);
        gA += 32;
        gB += 32;
        CP_COMMIT();
    };

    issue(0);
    issue(1);

    float acc[4][8][4];
#pragma unroll
    for (int mt = 0; mt < 4; mt++)
#pragma unroll
        for (int nt = 0; nt < 8; nt++)
#pragma unroll
            for (int i = 0; i < 4; i++) acc[mt][nt][i] = 0.f;

    int rbA[4], rbB[8];
#pragma unroll
    for (int mt = 0; mt < 4; mt++)
        rbA[mt] = (warp_m * 64 + mt * 16 + g) * 32;
#pragma unroll
    for (int nt = 0; nt < 8; nt++)
        rbB[nt] = (warp_n * 64 + nt * 8 + g) * 32;

    const int nk = GK / 32;
    for (int kt = 0; kt < nk; kt++) {
        if (kt < nk - 1) { CP_WAIT(1); } else { CP_WAIT(0); }
        __syncthreads();
        if (kt + 2 < nk) issue((kt + 2) % 3);

        const float* as = As + (kt % 3) * TILE_F;
        const float* bs = Bs + (kt % 3) * TILE_F;

#pragma unroll
        for (int k8 = 0; k8 < 4; k8++) {
            const int o0 = (((2 * k8)     ^ g) << 2) + t;
            const int o1 = (((2 * k8 + 1) ^ g) << 2) + t;

            float a[4][4];
#pragma unroll
            for (int mt = 0; mt < 4; mt++) {
                a[mt][0] = as[rbA[mt] + o0];
                a[mt][1] = as[rbA[mt] + 256 + o0];
                a[mt][2] = as[rbA[mt] + o1];
                a[mt][3] = as[rbA[mt] + 256 + o1];
            }
            float b[8][2];
#pragma unroll
            for (int nt = 0; nt < 8; nt++) {
                b[nt][0] = bs[rbB[nt] + o0];
                b[nt][1] = bs[rbB[nt] + o1];
            }
#pragma unroll
            for (int mt = 0; mt < 4; mt++)
#pragma unroll
                for (int nt = 0; nt < 8; nt++)
                    mma_tf32_r(acc[mt][nt],
                               a[mt][0], a[mt][1], a[mt][2], a[mt][3],
                               b[nt][0], b[nt][1]);
        }
    }

#pragma unroll
    for (int mt = 0; mt < 4; mt++) {
        int row = bm + warp_m * 64 + mt * 16 + g;
#pragma unroll
        for (int nt = 0; nt < 8; nt++) {
            int col = bn + warp_n * 64 + nt * 8 + 2 * t;
            float b0 = 0.f, b1 = 0.f;
            if (bias) { b0 = bias[col]; b1 = bias[col + 1]; }
            float v0 = acc[mt][nt][0] + b0, v1 = acc[mt][nt][1] + b1;
            float v2 = acc[mt][nt][2] + b0, v3 = acc[mt][nt][3] + b1;
            if (ROUND) {
                v0 = f2tf32(v0); v1 = f2tf32(v1);
                v2 = f2tf32(v2); v3 = f2tf32(v3);
            }
            *(float2*)(C + (size_t)row * HDIM + col)       = make_float2(v0, v1);
            *(float2*)(C + (size_t)(row + 8) * HDIM + col) = make_float2(v2, v3);
        }
    }
}

__global__ void __launch_bounds__(128, 2) qkv_gemm_kernel()
{
    const float* B = (blockIdx.z == 0) ? g_Wq : (blockIdx.z == 1) ? g_Wk : g_Wv;
    float* C       = (blockIdx.z == 0) ? g_Q  : (blockIdx.z == 1) ? g_K  : g_V;
    gemm_v3_body<true>(g_X, B, nullptr, C);
}

__global__ void __launch_bounds__(128, 2) out_gemm_kernel(
    const float* __restrict__ bo, float* __restrict__ out)
{
    gemm_v3_body<false>(g_C, g_Wo, bo, out);
}

// ---------------------------------------------------------------------------
// RoPE in-place on g_Q, g_K (writes tf32-rounded)
// ---------------------------------------------------------------------------
__global__ void rope_kernel(const int* __restrict__ pos_ids)
{
    int idx = blockIdx.x * 256 + threadIdx.x;
    if (idx >= MROWS * NH * 64) return;
    int d = idx & 63;
    int h = (idx >> 6) & 15;
    int m = idx >> 10;
    int s = m & (S_LEN - 1);

    float p = (float)pos_ids[s];
    float theta = expf(-0.14391156531392624f * (float)d);
    float ang = p * theta;
    float sn, cs;
    sincosf(ang, &sn, &cs);

    size_t base = (size_t)m * HDIM + h * DH + d;
    float q1 = g_Q[base], q2 = g_Q[base + 64];
    g_Q[base]      = f2tf32(q1 * cs - q2 * sn);
    g_Q[base + 64] = f2tf32(q1 * sn + q2 * cs);
    float k1 = g_K[base], k2 = g_K[base + 64];
    g_K[base]      = f2tf32(k1 * cs - k2 * sn);
    g_K[base + 64] = f2tf32(k1 * sn + k2 * cs);
}

// ---------------------------------------------------------------------------
// TF32 MMA flash attention. Sources pre-rounded (Q pre-scaled via Wq).
// ---------------------------------------------------------------------------
#define CQ 1034
#define CK 522
#define VSTRIDE 132
#define ATT_SMEM_FLOATS (16 * CQ + 16 * CK + 64 * VSTRIDE)
#define ATT_SMEM_BYTES  (ATT_SMEM_FLOATS * 4)

__global__ void __launch_bounds__(256) attn_kernel()
{
    extern __shared__ float sm[];
    float* Qs = sm;
    float* Ks = Qs + 16 * CQ;
    float* Vs = Ks + 16 * CK;

    const int tid  = threadIdx.x;
    const int lane = tid & 31;
    const int w    = tid >> 5;
    const int g    = lane >> 2;
    const int t    = lane & 3;
    const int qt   = (gridDim.x - 1) - blockIdx.x;
    const int h    = blockIdx.y;
    const int n    = blockIdx.z;
    const int q0   = qt * 128;

    const size_t rowbase = (size_t)n * S_LEN;
    const size_t hoff    = (size_t)h * DH;

#pragma unroll
    for (int it = 0; it < 16; it++) {
        int id = tid + it * 256;
        int r  = id >> 5;
        int f4 = id & 31;
        int so = (f4 >> 1) * CQ + r * 8 + (f4 & 1);
        float4 v = *(const float4*)(g_Q + (rowbase + q0 + r) * HDIM + hoff + f4 * 4);
        Qs[so + 0] = v.x;
        Qs[so + 2] = v.y;
        Qs[so + 4] = v.z;
        Qs[so + 6] = v.w;
    }

    float o[16][4];
#pragma unroll
    for (int dd = 0; dd < 16; dd++)
#pragma unroll
        for (int i = 0; i < 4; i++) o[dd][i] = 0.f;
    float m0 = -1e30f, m1 = -1e30f, l0 = 0.f, l1 = 0.f;

    const int row0 = q0 + w * 16 + g;
    const int nkt  = 2 * (qt + 1);

    for (int kt = 0; kt < nkt; kt++) {
        __syncthreads();
        const int k0 = kt * 64;
#pragma unroll
        for (int it = 0; it < 8; it++) {
            int id = tid + it * 256;
            int r  = id >> 5;
            int f4 = id & 31;
            size_t gg = (rowbase + k0 + r) * HDIM + hoff + f4 * 4;
            float4 vk = *(const float4*)(g_K + gg);
            int so = (f4 >> 1) * CK + r * 8 + (f4 & 1);
            Ks[so + 0] = vk.x;
            Ks[so + 2] = vk.y;
            Ks[so + 4] = vk.z;
            Ks[so + 6] = vk.w;
            *(float4*)&Vs[r * VSTRIDE + f4 * 4] = *(const float4*)(g_V + gg);
        }
        __syncthreads();

        float s[8][4];
#pragma unroll
        for (int nn = 0; nn < 8; nn++)
#pragma unroll
            for (int i = 0; i < 4; i++) s[nn][i] = 0.f;

#pragma unroll
        for (int c = 0; c < 16; c++) {
            const float* qp = &Qs[c * CQ + (w * 16 + g) * 8 + 2 * t];
            uint2 alo = *(const uint2*)qp;
            uint2 ahi = *(const uint2*)(qp + 64);
#pragma unroll
            for (int nn = 0; nn < 8; nn++) {
                uint2 b = *(const uint2*)&Ks[c * CK + (nn * 8 + g) * 8 + 2 * t];
                mma_tf32(s[nn], alo, ahi, b);
            }
        }

        if (k0 + 63 > row0) {
#pragma unroll
            for (int nn = 0; nn < 8; nn++) {
                int col = k0 + nn * 8 + 2 * t;
                if (col > row0)     s[nn][0] = -1e30f;
                if (col + 1 > row0) s[nn][1] = -1e30f;
                if (col > row0 + 8)     s[nn][2] = -1e30f;
                if (col + 1 > row0 + 8) s[nn][3] = -1e30f;
            }
        }

        float mx0 = -1e30f, mx1 = -1e30f;
#pragma unroll
        for (int nn = 0; nn < 8; nn++) {
            mx0 = fmaxf(mx0, fmaxf(s[nn][0], s[nn][1]));
            mx1 = fmaxf(mx1, fmaxf(s[nn][2], s[nn][3]));
        }
        mx0 = fmaxf(mx0, __shfl_xor_sync(0xffffffffu, mx0, 1));
        mx0 = fmaxf(mx0, __shfl_xor_sync(0xffffffffu, mx0, 2));
        mx1 = fmaxf(mx1, __shfl_xor_sync(0xffffffffu, mx1, 1));
        mx1 = fmaxf(mx1, __shfl_xor_sync(0xffffffffu, mx1, 2));

        float newm0 = fmaxf(m0, mx0);
        float newm1 = fmaxf(m1, mx1);
        float alpha0 = __expf(m0 - newm0);
        float alpha1 = __expf(m1 - newm1);
        m0 = newm0; m1 = newm1;

        float sum0 = 0.f, sum1 = 0.f;
#pragma unroll
        for (int nn = 0; nn < 8; nn++) {
            float p0 = f2tf32(__expf(s[nn][0] - newm0));
            float p1 = f2tf32(__expf(s[nn][1] - newm0));
            float p2 = f2tf32(__expf(s[nn][2] - newm1));
            float p3 = f2tf32(__expf(s[nn][3] - newm1));
            s[nn][0] = p0; s[nn][1] = p1; s[nn][2] = p2; s[nn][3] = p3;
            sum0 += p0 + p1;
            sum1 += p2 + p3;
        }
        sum0 += __shfl_xor_sync(0xffffffffu, sum0, 1);
        sum0 += __shfl_xor_sync(0xffffffffu, sum0, 2);
        sum1 += __shfl_xor_sync(0xffffffffu, sum1, 1);
        sum1 += __shfl_xor_sync(0xffffffffu, sum1, 2);
        l0 = l0 * alpha0 + sum0;
        l1 = l1 * alpha1 + sum1;

#pragma unroll
        for (int dd = 0; dd < 16; dd++) {
            o[dd][0] *= alpha0; o[dd][1] *= alpha0;
            o[dd][2] *= alpha1; o[dd][3] *= alpha1;
        }

#pragma unroll
        for (int c8 = 0; c8 < 8; c8++) {
            const float* vp = &Vs[(c8 * 8 + 2 * t) * VSTRIDE + g];
#pragma unroll
            for (int dd = 0; dd < 16; dd++) {
                float b0 = vp[dd * 8];
                float b1 = vp[dd * 8 + VSTRIDE];
                mma_tf32_r(o[dd], s[c8][0], s[c8][2], s[c8][1], s[c8][3], b0, b1);
            }
        }
    }

    float inv0 = 1.f / l0;
    float inv1 = 1.f / l1;
    size_t r0 = (rowbase + row0) * HDIM + hoff;
    size_t r1 = r0 + 8 * HDIM;
#pragma unroll
    for (int dd = 0; dd < 16; dd++) {
        int col = dd * 8 + 2 * t;
        *(float2*)(g_C + r0 + col) =
            make_float2(f2tf32(o[dd][0] * inv0), f2tf32(o[dd][1] * inv0));
        *(float2*)(g_C + r1 + col) =
            make_float2(f2tf32(o[dd][2] * inv1), f2tf32(o[dd][3] * inv1));
    }
}

// ---------------------------------------------------------------------------
// kernel_launch
// Inputs: 0=X 1=position_ids 2=mask(unused,causal) 3=Wq 4=Wk 5=Wv 6=Wo 7=bo
// ---------------------------------------------------------------------------
extern "C" void kernel_launch(void* const* d_in, const int* in_sizes, int n_in,
                              void* d_out, int out_size)
{
    const float* X   = (const float*)d_in[0];
    const int*   pos = (const int*)d_in[1];
    const float* Wq  = (const float*)d_in[3];
    const float* Wk  = (const float*)d_in[4];
    const float* Wv  = (const float*)d_in[5];
    const float* Wo  = (const float*)d_in[6];
    const float* bo  = (const float*)d_in[7];
    float* out = (float*)d_out;

    cudaFuncSetAttribute(qkv_gemm_kernel,
                         cudaFuncAttributeMaxDynamicSharedMemorySize,
                         GEMM_SMEM_BYTES);
    cudaFuncSetAttribute(out_gemm_kernel,
                         cudaFuncAttributeMaxDynamicSharedMemorySize,
                         GEMM_SMEM_BYTES);
    cudaFuncSetAttribute(attn_kernel,
                         cudaFuncAttributeMaxDynamicSharedMemorySize,
                         ATT_SMEM_BYTES);

    float *dX, *dWq, *dWk, *dWv, *dWo;
    cudaGetSymbolAddress((void**)&dX,  g_X);
    cudaGetSymbolAddress((void**)&dWq, g_Wq);
    cudaGetSymbolAddress((void**)&dWk, g_Wk);
    cudaGetSymbolAddress((void**)&dWv, g_Wv);
    cudaGetSymbolAddress((void**)&dWo, g_Wo);

    const float rs = 0.08838834764831845f;   // 1/sqrt(128)
    int nx4 = MROWS * HDIM / 4;
    int nw4 = HDIM * HDIM / 4;
    cvt_tf32_kernel<<<nx4 / 256, 256>>>(X,  dX,  nx4, 1.f);
    cvt_tf32_kernel<<<nw4 / 256, 256>>>(Wq, dWq, nw4, rs);
    cvt_tf32_kernel<<<nw4 / 256, 256>>>(Wk, dWk, nw4, 1.f);
    cvt_tf32_kernel<<<nw4 / 256, 256>>>(Wv, dWv, nw4, 1.f);
    cvt_tf32_kernel<<<nw4 / 256, 256>>>(Wo, dWo, nw4, 1.f);

    dim3 g_qkv(HDIM / 128, MROWS / 128, 3);
    qkv_gemm_kernel<<<g_qkv, 128, GEMM_SMEM_BYTES>>>();

    int rope_threads = MROWS * NH * 64;
    rope_kernel<<<(rope_threads + 255) / 256, 256>>>(pos);

    dim3 g_att(S_LEN / 128, NH, NB);
    attn_kernel<<<g_att, 256, ATT_SMEM_BYTES>>>();

    dim3 g_out(HDIM / 128, MROWS / 128);
    out_gemm_kernel<<<g_out, 128, GEMM_SMEM_BYTES>>>(bo, out);
}